// round 14
// baseline (speedup 1.0000x reference)
#include <cuda_runtime.h>
#include <cuda_fp16.h>
#include <cstdint>

// ---------------- problem constants ----------------
#define BLn    8192      // B * L
#define LSEQ   4096
#define DIMI   2048
#define DINn   8512      // 2*HID + 2*G*N + H
#define HIDC   4096
#define CONVD  4352      // HID + 2*G*N
#define NHh    64        // heads
#define PD     64        // head dim
#define NS     128       // state dim
#define QC     128       // chunk len
#define NCT    64        // total chunks = B * (L/Q)

// ---------------- scratch (device globals; allocation-free rule) ----------------
__device__ float g_zx[(size_t)BLn * DINn];
__device__ float g_conv[(size_t)BLn * CONVD];
__device__ float g_dt[BLn * NHh];
__device__ float g_cum[BLn * NHh];
__device__ float g_CB[NCT * QC * QC];
__device__ float g_states[(size_t)NCT * NHh * PD * NS];
__device__ float g_y[(size_t)BLn * HIDC];

// packed fp32 helpers (bit-identical to two scalar FMAs, half the issue slots)
__device__ __forceinline__ void ffma2(uint64_t& d, uint64_t a, uint64_t b) {
    asm("fma.rn.f32x2 %0, %1, %2, %0;" : "+l"(d) : "l"(a), "l"(b));
}
__device__ __forceinline__ uint64_t dupf(float v) {
    uint64_t r; asm("mov.b64 %0, {%1, %1};" : "=l"(r) : "f"(v)); return r;
}
__device__ __forceinline__ void fma4p(uint64_t* a2, uint64_t sd, const float4* v) {
    const uint64_t* v2 = reinterpret_cast<const uint64_t*>(v);
    ffma2(a2[0], sd, v2[0]);
    ffma2(a2[1], sd, v2[1]);
}

// =======================================================================
//  fp16 mma.sync m16n8k16 GEMM:  C[M slice, Nvalid] = A * B^T
//  fp32 in/out, fp16 operands, fp32 accum. CTA tile 256xNT, 8 warps (4x2).
// =======================================================================

__device__ __forceinline__ uint32_t pack_h2(float x, float y) {
    uint32_t r;
    asm("cvt.rn.f16x2.f32 %0, %1, %2;" : "=r"(r) : "f"(y), "f"(x));
    return r;
}

__device__ __forceinline__ void mma_f16(float* d, const uint32_t* a, const uint32_t* b) {
    asm volatile(
        "mma.sync.aligned.m16n8k16.row.col.f32.f16.f16.f32 "
        "{%0,%1,%2,%3}, {%4,%5,%6,%7}, {%8,%9}, {%0,%1,%2,%3};"
        : "+f"(d[0]), "+f"(d[1]), "+f"(d[2]), "+f"(d[3])
        : "r"(a[0]), "r"(a[1]), "r"(a[2]), "r"(a[3]), "r"(b[0]), "r"(b[1]));
}

#define AH 20                                 // half stride per smem row (16 + pad 4)

template<int NT>
__global__ void __launch_bounds__(256) gemm_tc(
    const float* __restrict__ A, const float* __restrict__ B, float* __restrict__ C,
    int Nvalid, int K, int ldC, int mOff)
{
    constexpr int NFRAG = NT / 16;            // n8-frags per warp
    constexpr int NB    = NT / 64;            // B staging v-iters
    constexpr int SSTH  = (256 + NT) * AH;    // halves per stage
    extern __shared__ __half hsm[];
    const int tid  = threadIdx.x;
    const int wid  = tid >> 5, lane = tid & 31;
    const int gID  = lane >> 2, tig = lane & 3;
    const int wM   = (wid >> 1) * 64;
    const int wN   = (wid & 1) * (NT / 2);
    const int cRow = mOff + blockIdx.y * 256;
    const int cCol = blockIdx.x * NT;
    const int KT   = K >> 4;

    const int srow = tid >> 2;
    const int sc4  = (tid & 3) * 4;
    bool bok[NB];
    #pragma unroll
    for (int v = 0; v < NB; v++) bok[v] = (cCol + v * 64 + srow) < Nvalid;

    float acc[4][NFRAG][4];
    #pragma unroll
    for (int mi = 0; mi < 4; mi++)
        #pragma unroll
        for (int ni = 0; ni < NFRAG; ni++)
            #pragma unroll
            for (int u = 0; u < 4; u++) acc[mi][ni][u] = 0.f;

    auto store_stage = [&](int slot, const float4* ra, const float4* rb) {
        __half* As = hsm + slot * SSTH;
        __half* Bs = As + 256 * AH;
        #pragma unroll
        for (int v = 0; v < 4; v++) {
            uint2 pk = make_uint2(pack_h2(ra[v].x, ra[v].y), pack_h2(ra[v].z, ra[v].w));
            *reinterpret_cast<uint2*>(&As[(v * 64 + srow) * AH + sc4]) = pk;
        }
        #pragma unroll
        for (int v = 0; v < NB; v++) {
            uint2 pk = make_uint2(pack_h2(rb[v].x, rb[v].y), pack_h2(rb[v].z, rb[v].w));
            *reinterpret_cast<uint2*>(&Bs[(v * 64 + srow) * AH + sc4]) = pk;
        }
    };

    float4 ra[4], rb[NB];
    // prologue: tile 0
    {
        #pragma unroll
        for (int v = 0; v < 4; v++)
            ra[v] = *reinterpret_cast<const float4*>(A + (size_t)(cRow + v * 64 + srow) * K + sc4);
        #pragma unroll
        for (int v = 0; v < NB; v++)
            rb[v] = bok[v] ? *reinterpret_cast<const float4*>(B + (size_t)(cCol + v * 64 + srow) * K + sc4)
                           : make_float4(0.f, 0.f, 0.f, 0.f);
        store_stage(0, ra, rb);
    }
    __syncthreads();

    for (int kt = 0; kt < KT; kt++) {
        const int b = kt & 1;
        const bool more = (kt + 1 < KT);
        if (more) {
            const int kb = (kt + 1) << 4;
            #pragma unroll
            for (int v = 0; v < 4; v++)
                ra[v] = *reinterpret_cast<const float4*>(A + (size_t)(cRow + v * 64 + srow) * K + kb + sc4);
            #pragma unroll
            for (int v = 0; v < NB; v++)
                rb[v] = bok[v] ? *reinterpret_cast<const float4*>(B + (size_t)(cCol + v * 64 + srow) * K + kb + sc4)
                               : make_float4(0.f, 0.f, 0.f, 0.f);
        }

        const __half* As = hsm + b * SSTH;
        const __half* Bs = As + 256 * AH;
        const int k0 = tig * 2;
        uint32_t af[4][4], bf[NFRAG][2];
        #pragma unroll
        for (int mi = 0; mi < 4; mi++) {
            const int r = wM + mi * 16 + gID;
            af[mi][0] = *reinterpret_cast<const uint32_t*>(&As[r * AH + k0]);
            af[mi][1] = *reinterpret_cast<const uint32_t*>(&As[(r + 8) * AH + k0]);
            af[mi][2] = *reinterpret_cast<const uint32_t*>(&As[r * AH + k0 + 8]);
            af[mi][3] = *reinterpret_cast<const uint32_t*>(&As[(r + 8) * AH + k0 + 8]);
        }
        #pragma unroll
        for (int ni = 0; ni < NFRAG; ni++) {
            const int r = wN + ni * 8 + gID;
            bf[ni][0] = *reinterpret_cast<const uint32_t*>(&Bs[r * AH + k0]);
            bf[ni][1] = *reinterpret_cast<const uint32_t*>(&Bs[r * AH + k0 + 8]);
        }
        #pragma unroll
        for (int mi = 0; mi < 4; mi++)
            #pragma unroll
            for (int ni = 0; ni < NFRAG; ni++)
                mma_f16(acc[mi][ni], af[mi], bf[ni]);

        if (more) store_stage(b ^ 1, ra, rb);
        __syncthreads();
    }

    // epilogue
    #pragma unroll
    for (int mi = 0; mi < 4; mi++) {
        const int r0 = cRow + wM + mi * 16 + gID;
        #pragma unroll
        for (int ni = 0; ni < NFRAG; ni++) {
            const int c = cCol + wN + ni * 8 + tig * 2;
            if (c < Nvalid) {
                *reinterpret_cast<float2*>(C + (size_t)r0 * ldC + c) =
                    make_float2(acc[mi][ni][0], acc[mi][ni][1]);
                *reinterpret_cast<float2*>(C + (size_t)(r0 + 8) * ldC + c) =
                    make_float2(acc[mi][ni][2], acc[mi][ni][3]);
            }
        }
    }
}

#define SMEM_NT128 (2 * (256 + 128) * AH * 2)   // 30720 B
#define SMEM_NT64  (2 * (256 + 64) * AH * 2)    // 25600 B

// ---------------- causal depthwise conv (K=4) + SiLU ----------------
__global__ void __launch_bounds__(256) conv_silu_kernel(const float* __restrict__ w) {
    size_t idx = (size_t)blockIdx.x * 256 + threadIdx.x;
    int c = (int)(idx % CONVD);
    int bl = (int)(idx / CONVD);
    int l = bl & (LSEQ - 1);
    float acc = 0.f;
    #pragma unroll
    for (int k = 0; k < 4; k++) {
        int lo = l - 3 + k;
        if (lo >= 0)
            acc += g_zx[(size_t)(bl - 3 + k) * DINn + HIDC + c] * w[c * 4 + k];
    }
    float s = 1.f / (1.f + expf(-acc));
    g_conv[(size_t)bl * CONVD + c] = acc * s;
}

// ---------------- dt = softplus(dt_raw + bias) ----------------
__global__ void __launch_bounds__(256) dt_kernel(const float* __restrict__ dt_bias) {
    int idx = blockIdx.x * 256 + threadIdx.x;
    int h = idx & 63;
    int bl = idx >> 6;
    float v = g_zx[(size_t)bl * DINn + (HIDC + CONVD) + h] + dt_bias[h];
    float d = (v > 20.f) ? v : log1pf(expf(v));
    g_dt[idx] = d;
}

// ---------------- per-chunk cumsum of dt*A (smem staged) ----------------
__global__ void __launch_bounds__(256) cum_kernel(const float* __restrict__ A_log) {
    __shared__ float s[QC * NHh];
    const int ch = blockIdx.x, tid = threadIdx.x;
    for (int idx = tid; idx < QC * NHh; idx += 256)
        s[idx] = g_dt[ch * QC * NHh + idx];
    __syncthreads();
    if (tid < NHh) {
        const float Ax = -expf(A_log[tid]);
        float run = 0.f;
        #pragma unroll 4
        for (int q = 0; q < QC; q++) {
            run += s[q * NHh + tid] * Ax;
            s[q * NHh + tid] = run;
        }
    }
    __syncthreads();
    for (int idx = tid; idx < QC * NHh; idx += 256)
        g_cum[ch * QC * NHh + idx] = s[idx];
}

// ---------------- per-chunk CB[i][j] = sum_n C[i,n]*B[j,n] ----------------
__global__ void __launch_bounds__(256) cb_kernel() {
    extern __shared__ float sh[];
    float* Bsh = sh;             // 128 x 129
    float* Csh = sh + 16512;     // 128 x 129
    int ch = blockIdx.x;
    int tid = threadIdx.x;
    for (int idx = tid; idx < 16384; idx += 256) {
        int i = idx >> 7, n = idx & 127;
        size_t row = (size_t)(ch * QC + i) * CONVD;
        Bsh[i * 129 + n] = g_conv[row + HIDC + n];
        Csh[i * 129 + n] = g_conv[row + HIDC + NS + n];
    }
    __syncthreads();
    int tx = tid & 15, ty = tid >> 4;
    float acc[8][8];
    #pragma unroll
    for (int i = 0; i < 8; i++)
        #pragma unroll
        for (int j = 0; j < 8; j++) acc[i][j] = 0.f;
    for (int n = 0; n < NS; n++) {
        float a[8], b[8];
        #pragma unroll
        for (int u = 0; u < 8; u++) a[u] = Csh[(ty * 8 + u) * 129 + n];
        #pragma unroll
        for (int u = 0; u < 8; u++) b[u] = Bsh[(tx * 8 + u) * 129 + n];
        #pragma unroll
        for (int i = 0; i < 8; i++)
            #pragma unroll
            for (int j = 0; j < 8; j++) acc[i][j] += a[i] * b[j];
    }
    #pragma unroll
    for (int i = 0; i < 8; i++)
        #pragma unroll
        for (int j0 = 0; j0 < 8; j0 += 4)
            *reinterpret_cast<float4*>(&g_CB[ch * 16384 + (ty * 8 + i) * 128 + tx * 8 + j0]) =
                make_float4(acc[i][j0], acc[i][j0 + 1], acc[i][j0 + 2], acc[i][j0 + 3]);
}

// ---------------- chunk states: states[h,p,n] = sum_q wdec[q]*xs[q,p]*B[q,n] ----------------
__global__ void __launch_bounds__(256) states_kernel() {
    __shared__ float Bs[32 * 128];
    __shared__ float xss[32 * 64];
    __shared__ float wdec[128];
    __shared__ float cl;
    const int h = blockIdx.x, ch = blockIdx.y;
    const int tid = threadIdx.x;
    if (tid == 0) cl = g_cum[(ch * QC + QC - 1) * NHh + h];
    __syncthreads();
    if (tid < 128) {
        int r = (ch * QC + tid) * NHh + h;
        wdec[tid] = __expf(cl - g_cum[r]) * g_dt[r];
    }
    const int p = tid >> 2, ng = tid & 3;
    uint64_t acc2[8][2];
    #pragma unroll
    for (int u = 0; u < 8; u++) { acc2[u][0] = 0ull; acc2[u][1] = 0ull; }

    for (int qt = 0; qt < 4; qt++) {
        __syncthreads();
        for (int idx = tid; idx < 4096; idx += 256) {
            int qq = idx >> 7, n = idx & 127;
            Bs[idx] = g_conv[(size_t)(ch * QC + qt * 32 + qq) * CONVD + HIDC + n];
        }
        for (int idx = tid; idx < 2048; idx += 256) {
            int qq = idx >> 6, pp = idx & 63;
            xss[idx] = g_conv[(size_t)(ch * QC + qt * 32 + qq) * CONVD + h * PD + pp];
        }
        __syncthreads();
        #pragma unroll 4
        for (int qq = 0; qq < 32; qq++) {
            const uint64_t cd = dupf(wdec[qt * 32 + qq] * xss[qq * 64 + p]);
            const float4* bp = (const float4*)&Bs[qq * 128 + ng * 32];
            #pragma unroll
            for (int u = 0; u < 8; u++) fma4p(acc2[u], cd, bp + u);
        }
    }
    size_t base = ((size_t)ch * NHh + h) * (PD * NS) + (size_t)p * NS + ng * 32;
    #pragma unroll
    for (int u = 0; u < 8; u++) {
        *reinterpret_cast<uint64_t*>(&g_states[base + u * 4])     = acc2[u][0];
        *reinterpret_cast<uint64_t*>(&g_states[base + u * 4 + 2]) = acc2[u][1];
    }
}

// ---------------- sequential inter-chunk scan (in-place: states -> Sprev) ----------------
__global__ void __launch_bounds__(256) scan_kernel() {
    const int h = blockIdx.x, b = blockIdx.y;
    const int t = threadIdx.x;
    float S[32];
    #pragma unroll
    for (int i = 0; i < 32; i++) S[i] = 0.f;
    for (int c = 0; c < 32; c++) {
        int ch = b * 32 + c;
        float dec = __expf(g_cum[(ch * QC + QC - 1) * NHh + h]);
        size_t base = ((size_t)ch * NHh + h) * (PD * NS);
        #pragma unroll
        for (int i = 0; i < 32; i++) {
            size_t id = base + (size_t)i * 256 + t;
            float st = g_states[id];
            g_states[id] = S[i];
            S[i] = S[i] * dec + st;
        }
    }
}

// ---------------- Yd + Yoff + D*xs -> y ----------------
__global__ void __launch_bounds__(256) ydyoff_kernel(const float* __restrict__ Dvec) {
    extern __shared__ float sh[];
    float* CBs   = sh;                 // 128 x 129
    float* Cs    = sh + 16512;         // 128 x 129
    float* SpT   = sh + 33024;         // [n][p] 128 x 64
    float* xss   = sh + 41216;         // [j][p] 128 x 64
    float* cum_s = sh + 49408;         // 128
    float* dt_s  = sh + 49536;         // 128
    const int h = blockIdx.x, ch = blockIdx.y, tid = threadIdx.x;

    for (int idx = tid; idx < 16384; idx += 256) {
        int i = idx >> 7, j = idx & 127;
        CBs[i * 129 + j] = g_CB[ch * 16384 + idx];
        Cs[i * 129 + j]  = g_conv[(size_t)(ch * QC + i) * CONVD + HIDC + NS + j];
    }
    for (int idx = tid; idx < 8192; idx += 256) {
        int p = idx >> 7, n = idx & 127;
        SpT[n * 64 + p] = g_states[((size_t)ch * NHh + h) * (PD * NS) + idx];
        xss[idx] = g_conv[(size_t)(ch * QC + (idx >> 6)) * CONVD + h * PD + (idx & 63)];
    }
    if (tid < 128) {
        int r = (ch * QC + tid) * NHh + h;
        cum_s[tid] = g_cum[r];
        dt_s[tid]  = g_dt[r];
    }
    __syncthreads();

    const int i = tid >> 1, ph = tid & 1;
    uint64_t aD2[8][2], aO2[8][2];
    #pragma unroll
    for (int u = 0; u < 8; u++) {
        aD2[u][0] = aD2[u][1] = 0ull;
        aO2[u][0] = aO2[u][1] = 0ull;
    }
    const float ci = cum_s[i];

    for (int j = 0; j <= i; j++) {
        const uint64_t md = dupf(CBs[i * 129 + j] * __expf(ci - cum_s[j]) * dt_s[j]);
        const float4* xr = (const float4*)&xss[j * 64 + ph * 32];
        #pragma unroll
        for (int u = 0; u < 8; u++) fma4p(aD2[u], md, xr + u);
    }
    #pragma unroll 4
    for (int n = 0; n < NS; n++) {
        const uint64_t cd = dupf(Cs[i * 129 + n]);
        const float4* sr = (const float4*)&SpT[n * 64 + ph * 32];
        #pragma unroll
        for (int u = 0; u < 8; u++) fma4p(aO2[u], cd, sr + u);
    }
    const float ei = __expf(ci);
    const float Dh = Dvec[h];
    const float* xi = &xss[i * 64 + ph * 32];
    float* yo = &g_y[(size_t)(ch * QC + i) * HIDC + h * PD + ph * 32];
    #pragma unroll
    for (int u = 0; u < 8; u++) {
        const float* d = reinterpret_cast<const float*>(aD2[u]);
        const float* o = reinterpret_cast<const float*>(aO2[u]);
        float4 r;
        r.x = d[0] + ei * o[0] + Dh * xi[u * 4 + 0];
        r.y = d[1] + ei * o[1] + Dh * xi[u * 4 + 1];
        r.z = d[2] + ei * o[2] + Dh * xi[u * 4 + 2];
        r.w = d[3] + ei * o[3] + Dh * xi[u * 4 + 3];
        *reinterpret_cast<float4*>(&yo[u * 4]) = r;
    }
}

// ---------------- gate with silu(z) + RMSNorm (in-place on g_y, row-offset) ----------------
__global__ void __launch_bounds__(256) gating_kernel(const float* __restrict__ norm_w, int blOff) {
    __shared__ float red[256];
    const int bl = blOff + blockIdx.x, tid = threadIdx.x;
    float vals[16];
    float ss = 0.f;
    #pragma unroll
    for (int it = 0; it < 16; it++) {
        int idx = it * 256 + tid;
        float yv = g_y[(size_t)bl * HIDC + idx];
        float z  = g_zx[(size_t)bl * DINn + idx];
        float yz = yv * (z / (1.f + expf(-z)));
        vals[it] = yz;
        ss += yz * yz;
    }
    red[tid] = ss;
    __syncthreads();
    for (int s = 128; s > 0; s >>= 1) {
        if (tid < s) red[tid] += red[tid + s];
        __syncthreads();
    }
    float sc = rsqrtf(red[0] / (float)HIDC + 1e-5f);
    #pragma unroll
    for (int it = 0; it < 16; it++) {
        int idx = it * 256 + tid;
        g_y[(size_t)bl * HIDC + idx] = vals[it] * sc * norm_w[idx];
    }
}

// ---------------- launch ----------------
extern "C" void kernel_launch(void* const* d_in, const int* in_sizes, int n_in,
                              void* d_out, int out_size) {
    const float* x       = (const float*)d_in[0];
    const float* W_in    = (const float*)d_in[1];
    const float* conv_w  = (const float*)d_in[2];
    const float* dt_bias = (const float*)d_in[3];
    const float* A_log   = (const float*)d_in[4];
    const float* Dv      = (const float*)d_in[5];
    const float* norm_w  = (const float*)d_in[6];
    const float* W_out   = (const float*)d_in[7];
    float* out = (float*)d_out;

    float *zx_p, *y_p;
    cudaGetSymbolAddress((void**)&zx_p, g_zx);
    cudaGetSymbolAddress((void**)&y_p, g_y);

    static cudaStream_t s2 = nullptr;
    static cudaEvent_t ev0 = nullptr, evB = nullptr, evC = nullptr, evD = nullptr;
    if (s2 == nullptr) {
        cudaStreamCreateWithFlags(&s2, cudaStreamNonBlocking);
        cudaEventCreateWithFlags(&ev0, cudaEventDisableTiming);
        cudaEventCreateWithFlags(&evB, cudaEventDisableTiming);
        cudaEventCreateWithFlags(&evC, cudaEventDisableTiming);
        cudaEventCreateWithFlags(&evD, cudaEventDisableTiming);
        cudaFuncSetAttribute(gemm_tc<128>, cudaFuncAttributeMaxDynamicSharedMemorySize, SMEM_NT128);
        cudaFuncSetAttribute(gemm_tc<64>,  cudaFuncAttributeMaxDynamicSharedMemorySize, SMEM_NT64);
        cudaFuncSetAttribute(cb_kernel, cudaFuncAttributeMaxDynamicSharedMemorySize, 132096);
        cudaFuncSetAttribute(ydyoff_kernel, cudaFuncAttributeMaxDynamicSharedMemorySize, 198656);
    }

    // fork s2 from the capture-origin stream (required for graph capture),
    // then 1a and 1b run CONCURRENTLY — 1b's CTAs backfill 1a's ragged tail.
    cudaEventRecord(ev0, 0);
    cudaStreamWaitEvent(s2, ev0, 0);

    // 1b) in-proj GEMM, z columns [0, 4096) — side stream
    gemm_tc<128><<<dim3(32, 32), 256, SMEM_NT128, s2>>>(
        x, W_in, zx_p, HIDC, DIMI, DINn, 0);
    cudaEventRecord(evB, s2);

    // 1a) in-proj GEMM, xBC+dt columns [4096, 8512) — default stream
    gemm_tc<128><<<dim3(35, 32), 256, SMEM_NT128>>>(
        x, W_in + (size_t)HIDC * DIMI, zx_p + HIDC, DINn - HIDC, DIMI, DINn, 0);

    // mid-chain on default stream (after 1a; overlaps tail of 1b)
    conv_silu_kernel<<<(BLn * CONVD) / 256, 256>>>(conv_w);
    dt_kernel<<<(BLn * NHh) / 256, 256>>>(dt_bias);
    cum_kernel<<<NCT, 256>>>(A_log);
    cb_kernel<<<NCT, 256, 132096>>>();
    states_kernel<<<dim3(NHh, NCT), 256>>>();
    scan_kernel<<<dim3(NHh, 2), 256>>>();
    ydyoff_kernel<<<dim3(NHh, NCT), 256, 198656>>>(Dv);
    cudaEventRecord(evD, 0);   // g_y complete (for s2's gating half)

    // gating split: half0 on default (needs z from 1b); half1 on s2 (needs y)
    cudaStreamWaitEvent(0, evB, 0);
    gating_kernel<<<BLn / 2, 256>>>(norm_w, 0);
    cudaStreamWaitEvent(s2, evD, 0);
    gating_kernel<<<BLn / 2, 256, 0, s2>>>(norm_w, BLn / 2);
    cudaEventRecord(evC, s2);

    // 2) out-proj GEMM, M-split: half0 overlaps gating half1; half1 after join
    gemm_tc<64><<<dim3(32, 16), 256, SMEM_NT64>>>(y_p, W_out, out, DIMI, HIDC, DIMI, 0);
    cudaStreamWaitEvent(0, evC, 0);   // join s2 back into origin stream
    gemm_tc<64><<<dim3(32, 16), 256, SMEM_NT64>>>(y_p, W_out, out, DIMI, HIDC, DIMI, 4096);
}

// round 15
// speedup vs baseline: 1.1205x; 1.1205x over previous
#include <cuda_runtime.h>
#include <cuda_fp16.h>
#include <cstdint>

// ---------------- problem constants ----------------
#define BLn    8192      // B * L
#define LSEQ   4096
#define DIMI   2048
#define DINn   8512      // 2*HID + 2*G*N + H
#define HIDC   4096
#define CONVD  4352      // HID + 2*G*N
#define NHh    64        // heads
#define PD     64        // head dim
#define NS     128       // state dim
#define QC     128       // chunk len
#define NCT    64        // total chunks = B * (L/Q)

// ---------------- scratch (device globals; allocation-free rule) ----------------
__device__ float g_zx[(size_t)BLn * DINn];
__device__ float g_conv[(size_t)BLn * CONVD];
__device__ float g_dt[BLn * NHh];
__device__ float g_cum[BLn * NHh];
__device__ float g_CB[NCT * QC * QC];
__device__ float g_states[(size_t)NCT * NHh * PD * NS];
__device__ float g_y[(size_t)BLn * HIDC];
// fp16 GEMM operand buffers
__device__ __half g_xh[(size_t)BLn * DIMI];
__device__ __half g_wih[(size_t)DINn * DIMI];
__device__ __half g_woh[(size_t)DIMI * HIDC];
__device__ __half g_ynh[(size_t)BLn * HIDC];

// packed fp32 helpers (bit-identical to two scalar FMAs, half the issue slots)
__device__ __forceinline__ void ffma2(uint64_t& d, uint64_t a, uint64_t b) {
    asm("fma.rn.f32x2 %0, %1, %2, %0;" : "+l"(d) : "l"(a), "l"(b));
}
__device__ __forceinline__ uint64_t dupf(float v) {
    uint64_t r; asm("mov.b64 %0, {%1, %1};" : "=l"(r) : "f"(v)); return r;
}
__device__ __forceinline__ void fma4p(uint64_t* a2, uint64_t sd, const float4* v) {
    const uint64_t* v2 = reinterpret_cast<const uint64_t*>(v);
    ffma2(a2[0], sd, v2[0]);
    ffma2(a2[1], sd, v2[1]);
}

__device__ __forceinline__ uint32_t pack_h2(float x, float y) {
    uint32_t r;
    asm("cvt.rn.f16x2.f32 %0, %1, %2;" : "=r"(r) : "f"(y), "f"(x));
    return r;
}

__device__ __forceinline__ void mma_f16(float* d, const uint32_t* a, const uint32_t* b) {
    asm volatile(
        "mma.sync.aligned.m16n8k16.row.col.f32.f16.f16.f32 "
        "{%0,%1,%2,%3}, {%4,%5,%6,%7}, {%8,%9}, {%0,%1,%2,%3};"
        : "+f"(d[0]), "+f"(d[1]), "+f"(d[2]), "+f"(d[3])
        : "r"(a[0]), "r"(a[1]), "r"(a[2]), "r"(a[3]), "r"(b[0]), "r"(b[1]));
}

// ---------------- fp32 -> fp16 conversion (8 elems/thread) ----------------
__global__ void __launch_bounds__(256) cvt_h_kernel(
    const float* __restrict__ src, __half* __restrict__ dst, int n8)
{
    int i = blockIdx.x * 256 + threadIdx.x;
    if (i < n8) {
        float4 a = reinterpret_cast<const float4*>(src)[i * 2];
        float4 b = reinterpret_cast<const float4*>(src)[i * 2 + 1];
        uint4 o;
        o.x = pack_h2(a.x, a.y); o.y = pack_h2(a.z, a.w);
        o.z = pack_h2(b.x, b.y); o.w = pack_h2(b.z, b.w);
        reinterpret_cast<uint4*>(dst)[i] = o;
    }
}

// =======================================================================
//  fp16-operand mma.sync GEMM: C[M, Nvalid] = A[M,K] * B[N,K]^T
//  A, B pre-converted fp16; fp32 accum/out. CTA tile 256xNT, 8 warps.
// =======================================================================

#define AH2 24                                // half stride per smem row (16 + pad 8)

template<int NT>
__global__ void __launch_bounds__(256) gemm_h(
    const __half* __restrict__ A, const __half* __restrict__ B, float* __restrict__ C,
    int Nvalid, int K, int ldC)
{
    constexpr int NFRAG = NT / 16;
    constexpr int SSTH  = (256 + NT) * AH2;
    extern __shared__ __half hsm[];
    const int tid  = threadIdx.x;
    const int wid  = tid >> 5, lane = tid & 31;
    const int gID  = lane >> 2, tig = lane & 3;
    const int wM   = (wid >> 1) * 64;
    const int wN   = (wid & 1) * (NT / 2);
    const int cRow = blockIdx.y * 256;
    const int cCol = blockIdx.x * NT;
    const int KT   = K >> 4;

    // staging: 8-half (16B) chunks; A: 512 chunks, B: NT*2 chunks
    const int arow = tid >> 1;              // 0..127 (A rows arow, 128+arow)
    const int off8 = (tid & 1) * 8;
    const int brow = tid >> 1;              // B row for NT=128: 0..127; NT=64: t<128
    const bool bact = (NT == 128) || (tid < 128);
    const bool bokv = bact && (cCol + brow) < Nvalid;

    float acc[4][NFRAG][4];
    #pragma unroll
    for (int mi = 0; mi < 4; mi++)
        #pragma unroll
        for (int ni = 0; ni < NFRAG; ni++)
            #pragma unroll
            for (int u = 0; u < 4; u++) acc[mi][ni][u] = 0.f;

    auto load_tile = [&](int kt, uint4* ra, uint4& rbv) {
        const int kb = kt << 4;
        #pragma unroll
        for (int v = 0; v < 2; v++)
            ra[v] = *reinterpret_cast<const uint4*>(A + (size_t)(cRow + v * 128 + arow) * K + kb + off8);
        rbv = make_uint4(0u, 0u, 0u, 0u);
        if (bokv)
            rbv = *reinterpret_cast<const uint4*>(B + (size_t)(cCol + brow) * K + kb + off8);
    };
    auto store_stage = [&](int slot, const uint4* ra, uint4 rbv) {
        __half* As = hsm + slot * SSTH;
        __half* Bs = As + 256 * AH2;
        #pragma unroll
        for (int v = 0; v < 2; v++)
            *reinterpret_cast<uint4*>(&As[(v * 128 + arow) * AH2 + off8]) = ra[v];
        if (bact)
            *reinterpret_cast<uint4*>(&Bs[brow * AH2 + off8]) = rbv;
    };

    uint4 ra[2], rbv;
    load_tile(0, ra, rbv);
    store_stage(0, ra, rbv);
    __syncthreads();

    for (int kt = 0; kt < KT; kt++) {
        const int b = kt & 1;
        const bool more = (kt + 1 < KT);
        if (more) load_tile(kt + 1, ra, rbv);

        const __half* As = hsm + b * SSTH;
        const __half* Bs = As + 256 * AH2;
        const int k0 = tig * 2;
        uint32_t af[4][4], bf[NFRAG][2];
        #pragma unroll
        for (int mi = 0; mi < 4; mi++) {
            const int r = wM + mi * 16 + gID;
            af[mi][0] = *reinterpret_cast<const uint32_t*>(&As[r * AH2 + k0]);
            af[mi][1] = *reinterpret_cast<const uint32_t*>(&As[(r + 8) * AH2 + k0]);
            af[mi][2] = *reinterpret_cast<const uint32_t*>(&As[r * AH2 + k0 + 8]);
            af[mi][3] = *reinterpret_cast<const uint32_t*>(&As[(r + 8) * AH2 + k0 + 8]);
        }
        #pragma unroll
        for (int ni = 0; ni < NFRAG; ni++) {
            const int r = wN + ni * 8 + gID;
            bf[ni][0] = *reinterpret_cast<const uint32_t*>(&Bs[r * AH2 + k0]);
            bf[ni][1] = *reinterpret_cast<const uint32_t*>(&Bs[r * AH2 + k0 + 8]);
        }
        #pragma unroll
        for (int mi = 0; mi < 4; mi++)
            #pragma unroll
            for (int ni = 0; ni < NFRAG; ni++)
                mma_f16(acc[mi][ni], af[mi], bf[ni]);

        if (more) store_stage(b ^ 1, ra, rbv);
        __syncthreads();
    }

    #pragma unroll
    for (int mi = 0; mi < 4; mi++) {
        const int r0 = cRow + wM + mi * 16 + gID;
        #pragma unroll
        for (int ni = 0; ni < NFRAG; ni++) {
            const int c = cCol + wN + ni * 8 + tig * 2;
            if (c < Nvalid) {
                *reinterpret_cast<float2*>(C + (size_t)r0 * ldC + c) =
                    make_float2(acc[mi][ni][0], acc[mi][ni][1]);
                *reinterpret_cast<float2*>(C + (size_t)(r0 + 8) * ldC + c) =
                    make_float2(acc[mi][ni][2], acc[mi][ni][3]);
            }
        }
    }
}

#define SMEMH_NT128 (2 * (256 + 128) * AH2 * 2)   // 36864 B
#define SMEMH_NT64  (2 * (256 + 64) * AH2 * 2)    // 30720 B

// ---------------- causal depthwise conv (K=4) + SiLU ----------------
__global__ void __launch_bounds__(256) conv_silu_kernel(const float* __restrict__ w) {
    size_t idx = (size_t)blockIdx.x * 256 + threadIdx.x;
    int c = (int)(idx % CONVD);
    int bl = (int)(idx / CONVD);
    int l = bl & (LSEQ - 1);
    float acc = 0.f;
    #pragma unroll
    for (int k = 0; k < 4; k++) {
        int lo = l - 3 + k;
        if (lo >= 0)
            acc += g_zx[(size_t)(bl - 3 + k) * DINn + HIDC + c] * w[c * 4 + k];
    }
    float s = 1.f / (1.f + expf(-acc));
    g_conv[(size_t)bl * CONVD + c] = acc * s;
}

// ---------------- dt = softplus(dt_raw + bias) ----------------
__global__ void __launch_bounds__(256) dt_kernel(const float* __restrict__ dt_bias) {
    int idx = blockIdx.x * 256 + threadIdx.x;
    int h = idx & 63;
    int bl = idx >> 6;
    float v = g_zx[(size_t)bl * DINn + (HIDC + CONVD) + h] + dt_bias[h];
    float d = (v > 20.f) ? v : log1pf(expf(v));
    g_dt[idx] = d;
}

// ---------------- per-chunk cumsum of dt*A (smem staged) ----------------
__global__ void __launch_bounds__(256) cum_kernel(const float* __restrict__ A_log) {
    __shared__ float s[QC * NHh];
    const int ch = blockIdx.x, tid = threadIdx.x;
    for (int idx = tid; idx < QC * NHh; idx += 256)
        s[idx] = g_dt[ch * QC * NHh + idx];
    __syncthreads();
    if (tid < NHh) {
        const float Ax = -expf(A_log[tid]);
        float run = 0.f;
        #pragma unroll 4
        for (int q = 0; q < QC; q++) {
            run += s[q * NHh + tid] * Ax;
            s[q * NHh + tid] = run;
        }
    }
    __syncthreads();
    for (int idx = tid; idx < QC * NHh; idx += 256)
        g_cum[ch * QC * NHh + idx] = s[idx];
}

// ---------------- per-chunk CB[i][j] = sum_n C[i,n]*B[j,n] ----------------
__global__ void __launch_bounds__(256) cb_kernel() {
    extern __shared__ float sh[];
    float* Bsh = sh;             // 128 x 129
    float* Csh = sh + 16512;     // 128 x 129
    int ch = blockIdx.x;
    int tid = threadIdx.x;
    for (int idx = tid; idx < 16384; idx += 256) {
        int i = idx >> 7, n = idx & 127;
        size_t row = (size_t)(ch * QC + i) * CONVD;
        Bsh[i * 129 + n] = g_conv[row + HIDC + n];
        Csh[i * 129 + n] = g_conv[row + HIDC + NS + n];
    }
    __syncthreads();
    int tx = tid & 15, ty = tid >> 4;
    float acc[8][8];
    #pragma unroll
    for (int i = 0; i < 8; i++)
        #pragma unroll
        for (int j = 0; j < 8; j++) acc[i][j] = 0.f;
    for (int n = 0; n < NS; n++) {
        float a[8], b[8];
        #pragma unroll
        for (int u = 0; u < 8; u++) a[u] = Csh[(ty * 8 + u) * 129 + n];
        #pragma unroll
        for (int u = 0; u < 8; u++) b[u] = Bsh[(tx * 8 + u) * 129 + n];
        #pragma unroll
        for (int i = 0; i < 8; i++)
            #pragma unroll
            for (int j = 0; j < 8; j++) acc[i][j] += a[i] * b[j];
    }
    #pragma unroll
    for (int i = 0; i < 8; i++)
        #pragma unroll
        for (int j0 = 0; j0 < 8; j0 += 4)
            *reinterpret_cast<float4*>(&g_CB[ch * 16384 + (ty * 8 + i) * 128 + tx * 8 + j0]) =
                make_float4(acc[i][j0], acc[i][j0 + 1], acc[i][j0 + 2], acc[i][j0 + 3]);
}

// ---------------- chunk states: states[h,p,n] = sum_q wdec[q]*xs[q,p]*B[q,n] ----------------
__global__ void __launch_bounds__(256) states_kernel() {
    __shared__ float Bs[32 * 128];
    __shared__ float xss[32 * 64];
    __shared__ float wdec[128];
    __shared__ float cl;
    const int h = blockIdx.x, ch = blockIdx.y;
    const int tid = threadIdx.x;
    if (tid == 0) cl = g_cum[(ch * QC + QC - 1) * NHh + h];
    __syncthreads();
    if (tid < 128) {
        int r = (ch * QC + tid) * NHh + h;
        wdec[tid] = __expf(cl - g_cum[r]) * g_dt[r];
    }
    const int p = tid >> 2, ng = tid & 3;
    uint64_t acc2[8][2];
    #pragma unroll
    for (int u = 0; u < 8; u++) { acc2[u][0] = 0ull; acc2[u][1] = 0ull; }

    for (int qt = 0; qt < 4; qt++) {
        __syncthreads();
        for (int idx = tid; idx < 4096; idx += 256) {
            int qq = idx >> 7, n = idx & 127;
            Bs[idx] = g_conv[(size_t)(ch * QC + qt * 32 + qq) * CONVD + HIDC + n];
        }
        for (int idx = tid; idx < 2048; idx += 256) {
            int qq = idx >> 6, pp = idx & 63;
            xss[idx] = g_conv[(size_t)(ch * QC + qt * 32 + qq) * CONVD + h * PD + pp];
        }
        __syncthreads();
        #pragma unroll 4
        for (int qq = 0; qq < 32; qq++) {
            const uint64_t cd = dupf(wdec[qt * 32 + qq] * xss[qq * 64 + p]);
            const float4* bp = (const float4*)&Bs[qq * 128 + ng * 32];
            #pragma unroll
            for (int u = 0; u < 8; u++) fma4p(acc2[u], cd, bp + u);
        }
    }
    size_t base = ((size_t)ch * NHh + h) * (PD * NS) + (size_t)p * NS + ng * 32;
    #pragma unroll
    for (int u = 0; u < 8; u++) {
        *reinterpret_cast<uint64_t*>(&g_states[base + u * 4])     = acc2[u][0];
        *reinterpret_cast<uint64_t*>(&g_states[base + u * 4 + 2]) = acc2[u][1];
    }
}

// ---------------- sequential inter-chunk scan (in-place: states -> Sprev) ----------------
__global__ void __launch_bounds__(256) scan_kernel() {
    const int h = blockIdx.x, b = blockIdx.y;
    const int t = threadIdx.x;
    float S[32];
    #pragma unroll
    for (int i = 0; i < 32; i++) S[i] = 0.f;
    for (int c = 0; c < 32; c++) {
        int ch = b * 32 + c;
        float dec = __expf(g_cum[(ch * QC + QC - 1) * NHh + h]);
        size_t base = ((size_t)ch * NHh + h) * (PD * NS);
        #pragma unroll
        for (int i = 0; i < 32; i++) {
            size_t id = base + (size_t)i * 256 + t;
            float st = g_states[id];
            g_states[id] = S[i];
            S[i] = S[i] * dec + st;
        }
    }
}

// ---------------- Yd + Yoff + D*xs -> y ----------------
__global__ void __launch_bounds__(256) ydyoff_kernel(const float* __restrict__ Dvec) {
    extern __shared__ float sh[];
    float* CBs   = sh;                 // 128 x 129
    float* Cs    = sh + 16512;         // 128 x 129
    float* SpT   = sh + 33024;         // [n][p] 128 x 64
    float* xss   = sh + 41216;         // [j][p] 128 x 64
    float* cum_s = sh + 49408;         // 128
    float* dt_s  = sh + 49536;         // 128
    const int h = blockIdx.x, ch = blockIdx.y, tid = threadIdx.x;

    for (int idx = tid; idx < 16384; idx += 256) {
        int i = idx >> 7, j = idx & 127;
        CBs[i * 129 + j] = g_CB[ch * 16384 + idx];
        Cs[i * 129 + j]  = g_conv[(size_t)(ch * QC + i) * CONVD + HIDC + NS + j];
    }
    for (int idx = tid; idx < 8192; idx += 256) {
        int p = idx >> 7, n = idx & 127;
        SpT[n * 64 + p] = g_states[((size_t)ch * NHh + h) * (PD * NS) + idx];
        xss[idx] = g_conv[(size_t)(ch * QC + (idx >> 6)) * CONVD + h * PD + (idx & 63)];
    }
    if (tid < 128) {
        int r = (ch * QC + tid) * NHh + h;
        cum_s[tid] = g_cum[r];
        dt_s[tid]  = g_dt[r];
    }
    __syncthreads();

    const int i = tid >> 1, ph = tid & 1;
    uint64_t aD2[8][2], aO2[8][2];
    #pragma unroll
    for (int u = 0; u < 8; u++) {
        aD2[u][0] = aD2[u][1] = 0ull;
        aO2[u][0] = aO2[u][1] = 0ull;
    }
    const float ci = cum_s[i];

    for (int j = 0; j <= i; j++) {
        const uint64_t md = dupf(CBs[i * 129 + j] * __expf(ci - cum_s[j]) * dt_s[j]);
        const float4* xr = (const float4*)&xss[j * 64 + ph * 32];
        #pragma unroll
        for (int u = 0; u < 8; u++) fma4p(aD2[u], md, xr + u);
    }
    #pragma unroll 4
    for (int n = 0; n < NS; n++) {
        const uint64_t cd = dupf(Cs[i * 129 + n]);
        const float4* sr = (const float4*)&SpT[n * 64 + ph * 32];
        #pragma unroll
        for (int u = 0; u < 8; u++) fma4p(aO2[u], cd, sr + u);
    }
    const float ei = __expf(ci);
    const float Dh = Dvec[h];
    const float* xi = &xss[i * 64 + ph * 32];
    float* yo = &g_y[(size_t)(ch * QC + i) * HIDC + h * PD + ph * 32];
    #pragma unroll
    for (int u = 0; u < 8; u++) {
        const float* d = reinterpret_cast<const float*>(aD2[u]);
        const float* o = reinterpret_cast<const float*>(aO2[u]);
        float4 r;
        r.x = d[0] + ei * o[0] + Dh * xi[u * 4 + 0];
        r.y = d[1] + ei * o[1] + Dh * xi[u * 4 + 1];
        r.z = d[2] + ei * o[2] + Dh * xi[u * 4 + 2];
        r.w = d[3] + ei * o[3] + Dh * xi[u * 4 + 3];
        *reinterpret_cast<float4*>(&yo[u * 4]) = r;
    }
}

// ---------------- gate with silu(z) + RMSNorm -> fp16 yn ----------------
__global__ void __launch_bounds__(256) gating_kernel(const float* __restrict__ norm_w) {
    __shared__ float red[256];
    const int bl = blockIdx.x, tid = threadIdx.x;
    float vals[16];
    float ss = 0.f;
    #pragma unroll
    for (int it = 0; it < 16; it++) {
        int idx = it * 256 + tid;
        float yv = g_y[(size_t)bl * HIDC + idx];
        float z  = g_zx[(size_t)bl * DINn + idx];
        float yz = yv * (z / (1.f + expf(-z)));
        vals[it] = yz;
        ss += yz * yz;
    }
    red[tid] = ss;
    __syncthreads();
    for (int s = 128; s > 0; s >>= 1) {
        if (tid < s) red[tid] += red[tid + s];
        __syncthreads();
    }
    float sc = rsqrtf(red[0] / (float)HIDC + 1e-5f);
    #pragma unroll
    for (int it = 0; it < 16; it++) {
        int idx = it * 256 + tid;
        g_ynh[(size_t)bl * HIDC + idx] = __float2half_rn(vals[it] * sc * norm_w[idx]);
    }
}

// ---------------- launch ----------------
extern "C" void kernel_launch(void* const* d_in, const int* in_sizes, int n_in,
                              void* d_out, int out_size) {
    const float* x       = (const float*)d_in[0];
    const float* W_in    = (const float*)d_in[1];
    const float* conv_w  = (const float*)d_in[2];
    const float* dt_bias = (const float*)d_in[3];
    const float* A_log   = (const float*)d_in[4];
    const float* Dv      = (const float*)d_in[5];
    const float* norm_w  = (const float*)d_in[6];
    const float* W_out   = (const float*)d_in[7];
    float* out = (float*)d_out;

    float *zx_p, *y_p;
    __half *xh_p, *wih_p, *woh_p, *ynh_p;
    cudaGetSymbolAddress((void**)&zx_p, g_zx);
    cudaGetSymbolAddress((void**)&y_p, g_y);
    cudaGetSymbolAddress((void**)&xh_p, g_xh);
    cudaGetSymbolAddress((void**)&wih_p, g_wih);
    cudaGetSymbolAddress((void**)&woh_p, g_woh);
    cudaGetSymbolAddress((void**)&ynh_p, g_ynh);

    static cudaStream_t s2 = nullptr;
    static cudaEvent_t evA = nullptr, evB = nullptr;
    if (s2 == nullptr) {
        cudaStreamCreateWithFlags(&s2, cudaStreamNonBlocking);
        cudaEventCreateWithFlags(&evA, cudaEventDisableTiming);
        cudaEventCreateWithFlags(&evB, cudaEventDisableTiming);
        cudaFuncSetAttribute(gemm_h<128>, cudaFuncAttributeMaxDynamicSharedMemorySize, SMEMH_NT128);
        cudaFuncSetAttribute(gemm_h<64>,  cudaFuncAttributeMaxDynamicSharedMemorySize, SMEMH_NT64);
        cudaFuncSetAttribute(cb_kernel, cudaFuncAttributeMaxDynamicSharedMemorySize, 132096);
        cudaFuncSetAttribute(ydyoff_kernel, cudaFuncAttributeMaxDynamicSharedMemorySize, 198656);
    }

    // 0) one-time fp16 conversions (x, W_in before GEMM1; W_out before GEMM2)
    cvt_h_kernel<<<(BLn * DIMI / 8 + 255) / 256, 256>>>(x, xh_p, BLn * DIMI / 8);
    cvt_h_kernel<<<(DINn * DIMI / 8 + 255) / 256, 256>>>(W_in, wih_p, DINn * DIMI / 8);

    // 1a) in-proj GEMM, xBC+dt columns [4096, 8512) — default stream
    gemm_h<128><<<dim3(35, 32), 256, SMEMH_NT128>>>(
        xh_p, wih_p + (size_t)HIDC * DIMI, zx_p + HIDC, DINn - HIDC, DIMI, DINn);
    cudaEventRecord(evA, 0);

    // 1b) in-proj GEMM, z columns [0, 4096) — side stream, overlapped with mid-chain
    cudaStreamWaitEvent(s2, evA, 0);
    gemm_h<128><<<dim3(32, 32), 256, SMEMH_NT128, s2>>>(
        xh_p, wih_p, zx_p, HIDC, DIMI, DINn);
    cudaEventRecord(evB, s2);

    // mid-chain on default stream (concurrent with 1b)
    conv_silu_kernel<<<(BLn * CONVD) / 256, 256>>>(conv_w);
    dt_kernel<<<(BLn * NHh) / 256, 256>>>(dt_bias);
    cum_kernel<<<NCT, 256>>>(A_log);
    cvt_h_kernel<<<(DIMI * HIDC / 8 + 255) / 256, 256>>>(W_out, woh_p, DIMI * HIDC / 8);
    cb_kernel<<<NCT, 256, 132096>>>();
    states_kernel<<<dim3(NHh, NCT), 256>>>();
    scan_kernel<<<dim3(NHh, 2), 256>>>();
    ydyoff_kernel<<<dim3(NHh, NCT), 256, 198656>>>(Dv);

    // join: gating needs z columns from 1b
    cudaStreamWaitEvent(0, evB, 0);
    gating_kernel<<<BLn, 256>>>(norm_w);

    // 2) out-proj GEMM: (8192 x 4096) * (2048 x 4096)^T — fp16 operands
    gemm_h<64><<<dim3(32, 32), 256, SMEMH_NT64>>>(ynh_p, woh_p, out, DIMI, HIDC, DIMI);
}

// round 16
// speedup vs baseline: 1.2553x; 1.1203x over previous
#include <cuda_runtime.h>
#include <cuda_fp16.h>
#include <cstdint>

// ---------------- problem constants ----------------
#define BLn    8192      // B * L
#define LSEQ   4096
#define DIMI   2048
#define DINn   8512      // 2*HID + 2*G*N + H
#define HIDC   4096
#define CONVD  4352      // HID + 2*G*N
#define NHh    64        // heads
#define PD     64        // head dim
#define NS     128       // state dim
#define QC     128       // chunk len
#define NCT    64        // total chunks = B * (L/Q)

// ---------------- scratch (device globals; allocation-free rule) ----------------
__device__ float g_zx[(size_t)BLn * DINn];
__device__ float g_conv[(size_t)BLn * CONVD];
__device__ float g_dt[BLn * NHh];
__device__ float g_cum[BLn * NHh];
__device__ float g_CB[NCT * QC * QC];
__device__ float g_states[(size_t)NCT * NHh * PD * NS];
__device__ float g_y[(size_t)BLn * HIDC];
// fp16 GEMM operand buffers
__device__ __half g_xh[(size_t)BLn * DIMI];
__device__ __half g_wih[(size_t)DINn * DIMI];
__device__ __half g_woh[(size_t)DIMI * HIDC];
__device__ __half g_ynh[(size_t)BLn * HIDC];

// packed fp32 helpers
__device__ __forceinline__ void ffma2(uint64_t& d, uint64_t a, uint64_t b) {
    asm("fma.rn.f32x2 %0, %1, %2, %0;" : "+l"(d) : "l"(a), "l"(b));
}
__device__ __forceinline__ uint64_t dupf(float v) {
    uint64_t r; asm("mov.b64 %0, {%1, %1};" : "=l"(r) : "f"(v)); return r;
}
__device__ __forceinline__ void fma4p(uint64_t* a2, uint64_t sd, const float4* v) {
    const uint64_t* v2 = reinterpret_cast<const uint64_t*>(v);
    ffma2(a2[0], sd, v2[0]);
    ffma2(a2[1], sd, v2[1]);
}

__device__ __forceinline__ uint32_t pack_h2(float x, float y) {
    uint32_t r;
    asm("cvt.rn.f16x2.f32 %0, %1, %2;" : "=r"(r) : "f"(y), "f"(x));
    return r;
}
__device__ __forceinline__ uint32_t smem_u32(const void* p) {
    uint32_t a;
    asm("{ .reg .u64 t; cvta.to.shared.u64 t, %1; cvt.u32.u64 %0, t; }" : "=r"(a) : "l"(p));
    return a;
}
__device__ __forceinline__ void mma_f16(float* d, const uint32_t* a, const uint32_t* b) {
    asm volatile(
        "mma.sync.aligned.m16n8k16.row.col.f32.f16.f16.f32 "
        "{%0,%1,%2,%3}, {%4,%5,%6,%7}, {%8,%9}, {%0,%1,%2,%3};"
        : "+f"(d[0]), "+f"(d[1]), "+f"(d[2]), "+f"(d[3])
        : "r"(a[0]), "r"(a[1]), "r"(a[2]), "r"(a[3]), "r"(b[0]), "r"(b[1]));
}
__device__ __forceinline__ void ldm_x4(uint32_t* r, uint32_t a) {
    asm volatile("ldmatrix.sync.aligned.m8n8.x4.shared.b16 {%0,%1,%2,%3}, [%4];"
        : "=r"(r[0]), "=r"(r[1]), "=r"(r[2]), "=r"(r[3]) : "r"(a));
}

// ---------------- fp32 -> fp16 conversion (8 elems/thread) ----------------
__global__ void __launch_bounds__(256) cvt_h_kernel(
    const float* __restrict__ src, __half* __restrict__ dst, int n8)
{
    int i = blockIdx.x * 256 + threadIdx.x;
    if (i < n8) {
        float4 a = reinterpret_cast<const float4*>(src)[i * 2];
        float4 b = reinterpret_cast<const float4*>(src)[i * 2 + 1];
        uint4 o;
        o.x = pack_h2(a.x, a.y); o.y = pack_h2(a.z, a.w);
        o.z = pack_h2(b.x, b.y); o.w = pack_h2(b.z, b.w);
        reinterpret_cast<uint4*>(dst)[i] = o;
    }
}

// =======================================================================
//  fp16-operand mma.sync GEMM with cp.async 4-stage pipeline + ldmatrix
//  C[M, Nvalid] = A[M,K] * B[N,K]^T. CTA tile 256xNT, 8 warps (4x2).
//  k-step 32, smem row stride 40 halves (80 B) — ldmatrix conflict-free.
// =======================================================================

#define RSB 80                                // row stride bytes (32 halves + pad 8)

template<int NT>
__global__ void __launch_bounds__(256) gemm_h(
    const __half* __restrict__ A, const __half* __restrict__ B, float* __restrict__ C,
    int Nvalid, int K, int ldC)
{
    constexpr int NFRAG  = NT / 16;
    constexpr int STAGEB = 256 * RSB + NT * RSB;
    extern __shared__ char smc[];
    const uint32_t smb = smem_u32(smc);
    const int tid  = threadIdx.x;
    const int wid  = tid >> 5, lane = tid & 31;
    const int gID  = lane >> 2, tig = lane & 3;
    const int wM   = (wid >> 1) * 64;
    const int wN   = (wid & 1) * (NT / 2);
    const int cRow = blockIdx.y * 256;
    const int cCol = blockIdx.x * NT;
    const int KT   = K >> 5;

    // ldmatrix lane offsets (bytes within a 16x16 / 16-col block)
    const uint32_t aoff = ((lane & 7) + ((lane >> 3) & 1) * 8) * RSB + ((lane >> 4) & 1) * 16;
    const uint32_t boff = ((lane & 7) + ((lane >> 4) & 1) * 8) * RSB + ((lane >> 3) & 1) * 16;

    float acc[4][NFRAG][4];
    #pragma unroll
    for (int mi = 0; mi < 4; mi++)
        #pragma unroll
        for (int ni = 0; ni < NFRAG; ni++)
            #pragma unroll
            for (int u = 0; u < 4; u++) acc[mi][ni][u] = 0.f;

    auto issue_stage = [&](int kt, int slot) {
        const int kb = kt << 5;                      // halves
        const uint32_t as = smb + (uint32_t)slot * STAGEB;
        const uint32_t bs = as + 256 * RSB;
        #pragma unroll
        for (int v = 0; v < 4; v++) {                // A: 1024 16B-chunks
            const int idx = v * 256 + tid;
            const int row = idx >> 2, c8 = (idx & 3) * 8;
            const __half* gp = A + (size_t)(cRow + row) * K + kb + c8;
            const uint32_t sa = as + row * RSB + c8 * 2;
            asm volatile("cp.async.cg.shared.global [%0], [%1], 16;" :: "r"(sa), "l"(gp));
        }
        #pragma unroll
        for (int v = 0; v < NT / 64; v++) {          // B: NT*4 16B-chunks
            const int idx = v * 256 + tid;
            const int row = idx >> 2, c8 = (idx & 3) * 8;
            const bool ok = (cCol + row) < Nvalid;
            const __half* gp = ok ? (B + (size_t)(cCol + row) * K + kb + c8) : B;
            const uint32_t sa = bs + row * RSB + c8 * 2;
            const int ssz = ok ? 16 : 0;
            asm volatile("cp.async.cg.shared.global [%0], [%1], 16, %2;" :: "r"(sa), "l"(gp), "r"(ssz));
        }
        asm volatile("cp.async.commit_group;" ::: "memory");
    };

    issue_stage(0, 0);
    issue_stage(1, 1);
    issue_stage(2, 2);

    for (int kt = 0; kt < KT; kt++) {
        asm volatile("cp.async.wait_group 2;" ::: "memory");
        __syncthreads();
        if (kt + 3 < KT) issue_stage(kt + 3, (kt + 3) & 3);
        else asm volatile("cp.async.commit_group;" ::: "memory");

        const uint32_t as = smb + (uint32_t)(kt & 3) * STAGEB;
        const uint32_t bs = as + 256 * RSB;
        #pragma unroll
        for (int kk = 0; kk < 2; kk++) {
            uint32_t af[4][4], bf[NFRAG][2];
            #pragma unroll
            for (int mi = 0; mi < 4; mi++)
                ldm_x4(af[mi], as + (wM + mi * 16) * RSB + kk * 32 + aoff);
            #pragma unroll
            for (int np = 0; np < NFRAG / 2; np++) {
                uint32_t r4[4];
                ldm_x4(r4, bs + (wN + np * 16) * RSB + kk * 32 + boff);
                bf[np * 2][0] = r4[0]; bf[np * 2][1] = r4[1];
                bf[np * 2 + 1][0] = r4[2]; bf[np * 2 + 1][1] = r4[3];
            }
            #pragma unroll
            for (int mi = 0; mi < 4; mi++)
                #pragma unroll
                for (int ni = 0; ni < NFRAG; ni++)
                    mma_f16(acc[mi][ni], af[mi], bf[ni]);
        }
        __syncthreads();
    }

    #pragma unroll
    for (int mi = 0; mi < 4; mi++) {
        const int r0 = cRow + wM + mi * 16 + gID;
        #pragma unroll
        for (int ni = 0; ni < NFRAG; ni++) {
            const int c = cCol + wN + ni * 8 + tig * 2;
            if (c < Nvalid) {
                *reinterpret_cast<float2*>(C + (size_t)r0 * ldC + c) =
                    make_float2(acc[mi][ni][0], acc[mi][ni][1]);
                *reinterpret_cast<float2*>(C + (size_t)(r0 + 8) * ldC + c) =
                    make_float2(acc[mi][ni][2], acc[mi][ni][3]);
            }
        }
    }
}

#define SMEMH_NT128 (4 * (256 * RSB + 128 * RSB))   // 122880 B
#define SMEMH_NT64  (4 * (256 * RSB + 64 * RSB))    // 102400 B

// ---------------- causal depthwise conv (K=4) + SiLU ----------------
__global__ void __launch_bounds__(256) conv_silu_kernel(const float* __restrict__ w) {
    size_t idx = (size_t)blockIdx.x * 256 + threadIdx.x;
    int c = (int)(idx % CONVD);
    int bl = (int)(idx / CONVD);
    int l = bl & (LSEQ - 1);
    float acc = 0.f;
    #pragma unroll
    for (int k = 0; k < 4; k++) {
        int lo = l - 3 + k;
        if (lo >= 0)
            acc += g_zx[(size_t)(bl - 3 + k) * DINn + HIDC + c] * w[c * 4 + k];
    }
    float s = 1.f / (1.f + expf(-acc));
    g_conv[(size_t)bl * CONVD + c] = acc * s;
}

// ---------------- dt = softplus(dt_raw + bias) ----------------
__global__ void __launch_bounds__(256) dt_kernel(const float* __restrict__ dt_bias) {
    int idx = blockIdx.x * 256 + threadIdx.x;
    int h = idx & 63;
    int bl = idx >> 6;
    float v = g_zx[(size_t)bl * DINn + (HIDC + CONVD) + h] + dt_bias[h];
    float d = (v > 20.f) ? v : log1pf(expf(v));
    g_dt[idx] = d;
}

// ---------------- per-chunk cumsum of dt*A (smem staged) ----------------
__global__ void __launch_bounds__(256) cum_kernel(const float* __restrict__ A_log) {
    __shared__ float s[QC * NHh];
    const int ch = blockIdx.x, tid = threadIdx.x;
    for (int idx = tid; idx < QC * NHh; idx += 256)
        s[idx] = g_dt[ch * QC * NHh + idx];
    __syncthreads();
    if (tid < NHh) {
        const float Ax = -expf(A_log[tid]);
        float run = 0.f;
        #pragma unroll 4
        for (int q = 0; q < QC; q++) {
            run += s[q * NHh + tid] * Ax;
            s[q * NHh + tid] = run;
        }
    }
    __syncthreads();
    for (int idx = tid; idx < QC * NHh; idx += 256)
        g_cum[ch * QC * NHh + idx] = s[idx];
}

// ---------------- per-chunk CB[i][j] = sum_n C[i,n]*B[j,n] ----------------
__global__ void __launch_bounds__(256) cb_kernel() {
    extern __shared__ float sh[];
    float* Bsh = sh;             // 128 x 129
    float* Csh = sh + 16512;     // 128 x 129
    int ch = blockIdx.x;
    int tid = threadIdx.x;
    for (int idx = tid; idx < 16384; idx += 256) {
        int i = idx >> 7, n = idx & 127;
        size_t row = (size_t)(ch * QC + i) * CONVD;
        Bsh[i * 129 + n] = g_conv[row + HIDC + n];
        Csh[i * 129 + n] = g_conv[row + HIDC + NS + n];
    }
    __syncthreads();
    int tx = tid & 15, ty = tid >> 4;
    float acc[8][8];
    #pragma unroll
    for (int i = 0; i < 8; i++)
        #pragma unroll
        for (int j = 0; j < 8; j++) acc[i][j] = 0.f;
    for (int n = 0; n < NS; n++) {
        float a[8], b[8];
        #pragma unroll
        for (int u = 0; u < 8; u++) a[u] = Csh[(ty * 8 + u) * 129 + n];
        #pragma unroll
        for (int u = 0; u < 8; u++) b[u] = Bsh[(tx * 8 + u) * 129 + n];
        #pragma unroll
        for (int i = 0; i < 8; i++)
            #pragma unroll
            for (int j = 0; j < 8; j++) acc[i][j] += a[i] * b[j];
    }
    #pragma unroll
    for (int i = 0; i < 8; i++)
        #pragma unroll
        for (int j0 = 0; j0 < 8; j0 += 4)
            *reinterpret_cast<float4*>(&g_CB[ch * 16384 + (ty * 8 + i) * 128 + tx * 8 + j0]) =
                make_float4(acc[i][j0], acc[i][j0 + 1], acc[i][j0 + 2], acc[i][j0 + 3]);
}

// ---------------- chunk states: states[h,p,n] = sum_q wdec[q]*xs[q,p]*B[q,n] ----------------
__global__ void __launch_bounds__(256) states_kernel() {
    __shared__ float Bs[32 * 128];
    __shared__ float xss[32 * 64];
    __shared__ float wdec[128];
    __shared__ float cl;
    const int h = blockIdx.x, ch = blockIdx.y;
    const int tid = threadIdx.x;
    if (tid == 0) cl = g_cum[(ch * QC + QC - 1) * NHh + h];
    __syncthreads();
    if (tid < 128) {
        int r = (ch * QC + tid) * NHh + h;
        wdec[tid] = __expf(cl - g_cum[r]) * g_dt[r];
    }
    const int p = tid >> 2, ng = tid & 3;
    uint64_t acc2[8][2];
    #pragma unroll
    for (int u = 0; u < 8; u++) { acc2[u][0] = 0ull; acc2[u][1] = 0ull; }

    for (int qt = 0; qt < 4; qt++) {
        __syncthreads();
        for (int idx = tid; idx < 4096; idx += 256) {
            int qq = idx >> 7, n = idx & 127;
            Bs[idx] = g_conv[(size_t)(ch * QC + qt * 32 + qq) * CONVD + HIDC + n];
        }
        for (int idx = tid; idx < 2048; idx += 256) {
            int qq = idx >> 6, pp = idx & 63;
            xss[idx] = g_conv[(size_t)(ch * QC + qt * 32 + qq) * CONVD + h * PD + pp];
        }
        __syncthreads();
        #pragma unroll 4
        for (int qq = 0; qq < 32; qq++) {
            const uint64_t cd = dupf(wdec[qt * 32 + qq] * xss[qq * 64 + p]);
            const float4* bp = (const float4*)&Bs[qq * 128 + ng * 32];
            #pragma unroll
            for (int u = 0; u < 8; u++) fma4p(acc2[u], cd, bp + u);
        }
    }
    size_t base = ((size_t)ch * NHh + h) * (PD * NS) + (size_t)p * NS + ng * 32;
    #pragma unroll
    for (int u = 0; u < 8; u++) {
        *reinterpret_cast<uint64_t*>(&g_states[base + u * 4])     = acc2[u][0];
        *reinterpret_cast<uint64_t*>(&g_states[base + u * 4 + 2]) = acc2[u][1];
    }
}

// ---------------- sequential inter-chunk scan (in-place: states -> Sprev) ----------------
__global__ void __launch_bounds__(256) scan_kernel() {
    const int h = blockIdx.x, b = blockIdx.y;
    const int t = threadIdx.x;
    float S[32];
    #pragma unroll
    for (int i = 0; i < 32; i++) S[i] = 0.f;
    for (int c = 0; c < 32; c++) {
        int ch = b * 32 + c;
        float dec = __expf(g_cum[(ch * QC + QC - 1) * NHh + h]);
        size_t base = ((size_t)ch * NHh + h) * (PD * NS);
        #pragma unroll
        for (int i = 0; i < 32; i++) {
            size_t id = base + (size_t)i * 256 + t;
            float st = g_states[id];
            g_states[id] = S[i];
            S[i] = S[i] * dec + st;
        }
    }
}

// ---------------- Yd + Yoff + D*xs -> y ----------------
__global__ void __launch_bounds__(256) ydyoff_kernel(const float* __restrict__ Dvec) {
    extern __shared__ float sh[];
    float* CBs   = sh;                 // 128 x 129
    float* Cs    = sh + 16512;         // 128 x 129
    float* SpT   = sh + 33024;         // [n][p] 128 x 64
    float* xss   = sh + 41216;         // [j][p] 128 x 64
    float* cum_s = sh + 49408;         // 128
    float* dt_s  = sh + 49536;         // 128
    const int h = blockIdx.x, ch = blockIdx.y, tid = threadIdx.x;

    for (int idx = tid; idx < 16384; idx += 256) {
        int i = idx >> 7, j = idx & 127;
        CBs[i * 129 + j] = g_CB[ch * 16384 + idx];
        Cs[i * 129 + j]  = g_conv[(size_t)(ch * QC + i) * CONVD + HIDC + NS + j];
    }
    for (int idx = tid; idx < 8192; idx += 256) {
        int p = idx >> 7, n = idx & 127;
        SpT[n * 64 + p] = g_states[((size_t)ch * NHh + h) * (PD * NS) + idx];
        xss[idx] = g_conv[(size_t)(ch * QC + (idx >> 6)) * CONVD + h * PD + (idx & 63)];
    }
    if (tid < 128) {
        int r = (ch * QC + tid) * NHh + h;
        cum_s[tid] = g_cum[r];
        dt_s[tid]  = g_dt[r];
    }
    __syncthreads();

    const int i = tid >> 1, ph = tid & 1;
    uint64_t aD2[8][2], aO2[8][2];
    #pragma unroll
    for (int u = 0; u < 8; u++) {
        aD2[u][0] = aD2[u][1] = 0ull;
        aO2[u][0] = aO2[u][1] = 0ull;
    }
    const float ci = cum_s[i];

    for (int j = 0; j <= i; j++) {
        const uint64_t md = dupf(CBs[i * 129 + j] * __expf(ci - cum_s[j]) * dt_s[j]);
        const float4* xr = (const float4*)&xss[j * 64 + ph * 32];
        #pragma unroll
        for (int u = 0; u < 8; u++) fma4p(aD2[u], md, xr + u);
    }
    #pragma unroll 4
    for (int n = 0; n < NS; n++) {
        const uint64_t cd = dupf(Cs[i * 129 + n]);
        const float4* sr = (const float4*)&SpT[n * 64 + ph * 32];
        #pragma unroll
        for (int u = 0; u < 8; u++) fma4p(aO2[u], cd, sr + u);
    }
    const float ei = __expf(ci);
    const float Dh = Dvec[h];
    const float* xi = &xss[i * 64 + ph * 32];
    float* yo = &g_y[(size_t)(ch * QC + i) * HIDC + h * PD + ph * 32];
    #pragma unroll
    for (int u = 0; u < 8; u++) {
        const float* d = reinterpret_cast<const float*>(aD2[u]);
        const float* o = reinterpret_cast<const float*>(aO2[u]);
        float4 r;
        r.x = d[0] + ei * o[0] + Dh * xi[u * 4 + 0];
        r.y = d[1] + ei * o[1] + Dh * xi[u * 4 + 1];
        r.z = d[2] + ei * o[2] + Dh * xi[u * 4 + 2];
        r.w = d[3] + ei * o[3] + Dh * xi[u * 4 + 3];
        *reinterpret_cast<float4*>(&yo[u * 4]) = r;
    }
}

// ---------------- gate with silu(z) + RMSNorm -> fp16 yn ----------------
__global__ void __launch_bounds__(256) gating_kernel(const float* __restrict__ norm_w) {
    __shared__ float red[256];
    const int bl = blockIdx.x, tid = threadIdx.x;
    float vals[16];
    float ss = 0.f;
    #pragma unroll
    for (int it = 0; it < 16; it++) {
        int idx = it * 256 + tid;
        float yv = g_y[(size_t)bl * HIDC + idx];
        float z  = g_zx[(size_t)bl * DINn + idx];
        float yz = yv * (z / (1.f + expf(-z)));
        vals[it] = yz;
        ss += yz * yz;
    }
    red[tid] = ss;
    __syncthreads();
    for (int s = 128; s > 0; s >>= 1) {
        if (tid < s) red[tid] += red[tid + s];
        __syncthreads();
    }
    float sc = rsqrtf(red[0] / (float)HIDC + 1e-5f);
    #pragma unroll
    for (int it = 0; it < 16; it++) {
        int idx = it * 256 + tid;
        g_ynh[(size_t)bl * HIDC + idx] = __float2half_rn(vals[it] * sc * norm_w[idx]);
    }
}

// ---------------- launch ----------------
extern "C" void kernel_launch(void* const* d_in, const int* in_sizes, int n_in,
                              void* d_out, int out_size) {
    const float* x       = (const float*)d_in[0];
    const float* W_in    = (const float*)d_in[1];
    const float* conv_w  = (const float*)d_in[2];
    const float* dt_bias = (const float*)d_in[3];
    const float* A_log   = (const float*)d_in[4];
    const float* Dv      = (const float*)d_in[5];
    const float* norm_w  = (const float*)d_in[6];
    const float* W_out   = (const float*)d_in[7];
    float* out = (float*)d_out;

    float *zx_p, *y_p;
    __half *xh_p, *wih_p, *woh_p, *ynh_p;
    cudaGetSymbolAddress((void**)&zx_p, g_zx);
    cudaGetSymbolAddress((void**)&y_p, g_y);
    cudaGetSymbolAddress((void**)&xh_p, g_xh);
    cudaGetSymbolAddress((void**)&wih_p, g_wih);
    cudaGetSymbolAddress((void**)&woh_p, g_woh);
    cudaGetSymbolAddress((void**)&ynh_p, g_ynh);

    static cudaStream_t s2 = nullptr;
    static cudaEvent_t evA = nullptr, evB = nullptr;
    if (s2 == nullptr) {
        cudaStreamCreateWithFlags(&s2, cudaStreamNonBlocking);
        cudaEventCreateWithFlags(&evA, cudaEventDisableTiming);
        cudaEventCreateWithFlags(&evB, cudaEventDisableTiming);
        cudaFuncSetAttribute(gemm_h<128>, cudaFuncAttributeMaxDynamicSharedMemorySize, SMEMH_NT128);
        cudaFuncSetAttribute(gemm_h<64>,  cudaFuncAttributeMaxDynamicSharedMemorySize, SMEMH_NT64);
        cudaFuncSetAttribute(cb_kernel, cudaFuncAttributeMaxDynamicSharedMemorySize, 132096);
        cudaFuncSetAttribute(ydyoff_kernel, cudaFuncAttributeMaxDynamicSharedMemorySize, 198656);
    }

    // 0) one-time fp16 conversions
    cvt_h_kernel<<<(BLn * DIMI / 8 + 255) / 256, 256>>>(x, xh_p, BLn * DIMI / 8);
    cvt_h_kernel<<<(DINn * DIMI / 8 + 255) / 256, 256>>>(W_in, wih_p, DINn * DIMI / 8);

    // 1a) in-proj GEMM, xBC+dt columns [4096, 8512) — default stream
    gemm_h<128><<<dim3(35, 32), 256, SMEMH_NT128>>>(
        xh_p, wih_p + (size_t)HIDC * DIMI, zx_p + HIDC, DINn - HIDC, DIMI, DINn);
    cudaEventRecord(evA, 0);

    // 1b) in-proj GEMM, z columns [0, 4096) — side stream, overlapped with mid-chain
    cudaStreamWaitEvent(s2, evA, 0);
    gemm_h<128><<<dim3(32, 32), 256, SMEMH_NT128, s2>>>(
        xh_p, wih_p, zx_p, HIDC, DIMI, DINn);
    cudaEventRecord(evB, s2);

    // mid-chain on default stream (concurrent with 1b)
    conv_silu_kernel<<<(BLn * CONVD) / 256, 256>>>(conv_w);
    dt_kernel<<<(BLn * NHh) / 256, 256>>>(dt_bias);
    cum_kernel<<<NCT, 256>>>(A_log);
    cvt_h_kernel<<<(DIMI * HIDC / 8 + 255) / 256, 256>>>(W_out, woh_p, DIMI * HIDC / 8);
    cb_kernel<<<NCT, 256, 132096>>>();
    states_kernel<<<dim3(NHh, NCT), 256>>>();
    scan_kernel<<<dim3(NHh, 2), 256>>>();
    ydyoff_kernel<<<dim3(NHh, NCT), 256, 198656>>>(Dv);

    // join: gating needs z columns from 1b
    cudaStreamWaitEvent(0, evB, 0);
    gating_kernel<<<BLn, 256>>>(norm_w);

    // 2) out-proj GEMM: (8192 x 4096) * (2048 x 4096)^T — fp16 operands
    gemm_h<64><<<dim3(32, 32), 256, SMEMH_NT64>>>(ynh_p, woh_p, out, DIMI, HIDC, DIMI);
}